// round 15
// baseline (speedup 1.0000x reference)
#include <cuda_runtime.h>
#include <cuda_fp16.h>
#include <math.h>
#include <stdint.h>

// PointLoss_like_GPS — GB300 sm_103a, Round 15
// R14 engine (fp16x2, 2 queries/thread, 8 accum chains) on a PERSISTENT grid:
// 608 blocks (4/SM x 152) steal 1024 scan-items dynamically -> no wave
// raggedness. Ticketed finalize unchanged; counters self-clean for replay.

#define NPTS    4096
#define DIMS    3
#define THREADS 256
#define SPLITS  16
#define RSPLIT  (NPTS / SPLITS)      // 256 refs per item
#define QPT     2
#define QPB     (THREADS * QPT)      // 512 queries per item
#define NITEMS_MAX 1024
#define MAXQ    32768
#define FINB    32
#define GRID    608                  // 4 blocks/SM x 152 SMs, all co-resident

__device__ float        g_dmin[MAXQ * SPLITS];
__device__ float        g_fpart[FINB];
__device__ unsigned int g_work;          // work-stealing counter
__device__ unsigned int g_ticket1;       // block-completion ticket
__device__ unsigned int g_ticket2;       // finalizer-completion ticket

__device__ __forceinline__ __half2 h2_of(unsigned int u)
{
    return *reinterpret_cast<const __half2*>(&u);
}

__global__ void __launch_bounds__(THREADS, 4)
gps_kernel(const float* __restrict__ a1,
           const float* __restrict__ a2,
           const float* __restrict__ alpha_p,
           const float* __restrict__ beta_p,
           float* __restrict__ out,
           int nq, int nitems, float scale)
{
    __shared__ __align__(16) __half2 shX[RSPLIT / 2];
    __shared__ __align__(16) __half2 shY[RSPLIT / 2];
    __shared__ __align__(16) __half2 shZ[RSPLIT / 2];
    __shared__ float red[THREADS / 32];
    __shared__ unsigned int s_item;
    __shared__ unsigned int s_ticket;

    const int tid = threadIdx.x;

    for (;;) {
        __syncthreads();                       // protect shX reuse + s_item
        if (tid == 0) s_item = atomicAdd(&g_work, 1u);
        __syncthreads();
        const unsigned int it = s_item;
        if (it >= (unsigned)nitems) break;

        // item = pair*(8*SPLITS) + qc*SPLITS + sp
        const int sp   = it & (SPLITS - 1);
        const int qc   = (it >> 4) & 7;
        const int pair = it >> 7;
        const int b    = pair >> 1;

        const int qA = qc * QPB + tid;
        const int qB = qA + THREADS;

        const float* base1 = a1 + (size_t)b * NPTS * DIMS;
        const float* base2 = a2 + (size_t)b * NPTS * DIMS;
        const float* samples = (pair & 1) ? base1 : base2;
        const float* refs    = ((pair & 1) ? base2 : base1)
                               + (size_t)sp * RSPLIT * DIMS;

        const float qAx = samples[qA * 3 + 0];
        const float qAy = samples[qA * 3 + 1];
        const float qAz = samples[qA * 3 + 2];
        const float qBx = samples[qB * 3 + 0];
        const float qBy = samples[qB * 3 + 1];
        const float qBz = samples[qB * 3 + 2];

        const __half2 ax2 = __floats2half2_rn(qAx, qAx);
        const __half2 ay2 = __floats2half2_rn(qAy, qAy);
        const __half2 az2 = __floats2half2_rn(qAz, qAz);
        const __half2 bx2 = __floats2half2_rn(qBx, qBx);
        const __half2 by2 = __floats2half2_rn(qBy, qBy);
        const __half2 bz2 = __floats2half2_rn(qBz, qBz);

        if (tid < RSPLIT / 2) {
            const float* p = refs + (size_t)tid * 6;
            shX[tid] = __floats2half2_rn(p[0], p[3]);
            shY[tid] = __floats2half2_rn(p[1], p[4]);
            shZ[tid] = __floats2half2_rn(p[2], p[5]);
        }
        __syncthreads();

        const __half2 HMAXV = __float2half2_rn(65504.0f);
        __half2 am0 = HMAXV, am1 = HMAXV, am2 = HMAXV, am3 = HMAXV;
        __half2 bm0 = HMAXV, bm1 = HMAXV, bm2 = HMAXV, bm3 = HMAXV;

        const uint4* X = (const uint4*)shX;
        const uint4* Y = (const uint4*)shY;
        const uint4* Z = (const uint4*)shZ;

        #pragma unroll 4
        for (int j = 0; j < RSPLIT / 8; j++) {
            const uint4 xv = X[j], yv = Y[j], zv = Z[j];

            {   // query A
                const __half2 dx0 = __habs2(__hsub2(ax2, h2_of(xv.x)));
                const __half2 dy0 = __habs2(__hsub2(ay2, h2_of(yv.x)));
                const __half2 dz0 = __habs2(__hsub2(az2, h2_of(zv.x)));
                am0 = __hmin2(am0, __hadd2(__hadd2(dx0, dy0), dz0));

                const __half2 dx1 = __habs2(__hsub2(ax2, h2_of(xv.y)));
                const __half2 dy1 = __habs2(__hsub2(ay2, h2_of(yv.y)));
                const __half2 dz1 = __habs2(__hsub2(az2, h2_of(zv.y)));
                am1 = __hmin2(am1, __hadd2(__hadd2(dx1, dy1), dz1));

                const __half2 dx2 = __habs2(__hsub2(ax2, h2_of(xv.z)));
                const __half2 dy2 = __habs2(__hsub2(ay2, h2_of(yv.z)));
                const __half2 dz2 = __habs2(__hsub2(az2, h2_of(zv.z)));
                am2 = __hmin2(am2, __hadd2(__hadd2(dx2, dy2), dz2));

                const __half2 dx3 = __habs2(__hsub2(ax2, h2_of(xv.w)));
                const __half2 dy3 = __habs2(__hsub2(ay2, h2_of(yv.w)));
                const __half2 dz3 = __habs2(__hsub2(az2, h2_of(zv.w)));
                am3 = __hmin2(am3, __hadd2(__hadd2(dx3, dy3), dz3));
            }
            {   // query B
                const __half2 dx0 = __habs2(__hsub2(bx2, h2_of(xv.x)));
                const __half2 dy0 = __habs2(__hsub2(by2, h2_of(yv.x)));
                const __half2 dz0 = __habs2(__hsub2(bz2, h2_of(zv.x)));
                bm0 = __hmin2(bm0, __hadd2(__hadd2(dx0, dy0), dz0));

                const __half2 dx1 = __habs2(__hsub2(bx2, h2_of(xv.y)));
                const __half2 dy1 = __habs2(__hsub2(by2, h2_of(yv.y)));
                const __half2 dz1 = __habs2(__hsub2(bz2, h2_of(zv.y)));
                bm1 = __hmin2(bm1, __hadd2(__hadd2(dx1, dy1), dz1));

                const __half2 dx2 = __habs2(__hsub2(bx2, h2_of(xv.z)));
                const __half2 dy2 = __habs2(__hsub2(by2, h2_of(yv.z)));
                const __half2 dz2 = __habs2(__hsub2(bz2, h2_of(zv.z)));
                bm2 = __hmin2(bm2, __hadd2(__hadd2(dx2, dy2), dz2));

                const __half2 dx3 = __habs2(__hsub2(bx2, h2_of(xv.w)));
                const __half2 dy3 = __habs2(__hsub2(by2, h2_of(yv.w)));
                const __half2 dz3 = __habs2(__hsub2(bz2, h2_of(zv.w)));
                bm3 = __hmin2(bm3, __hadd2(__hadd2(dx3, dy3), dz3));
            }
        }

        const __half2 amv = __hmin2(__hmin2(am0, am1), __hmin2(am2, am3));
        const __half2 bmv = __hmin2(__hmin2(bm0, bm1), __hmin2(bm2, bm3));
        const float dminA = fminf(__low2float(amv), __high2float(amv));
        const float dminB = fminf(__low2float(bmv), __high2float(bmv));

        const size_t qrow = (size_t)(pair * NPTS);
        g_dmin[(qrow + qA) * SPLITS + sp] = dminA;
        g_dmin[(qrow + qB) * SPLITS + sp] = dminB;
    }

    // ---- block done: ticket; last FINB blocks finalize ----
    if (tid == 0) {
        __threadfence();
        s_ticket = atomicAdd(&g_ticket1, 1u);
    }
    __syncthreads();
    const unsigned int t = s_ticket;
    if (t < (unsigned)(GRID - FINB)) return;

    const int rank = (int)t - (GRID - FINB);

    if (tid == 0) {
        while (*((volatile unsigned int*)&g_ticket1) < (unsigned)GRID) { }
    }
    __syncthreads();
    __threadfence();

    const float alpha = *alpha_p;
    const float beta  = *beta_p;
    const float delta = __powf(alpha, -1.0f / beta);

    const int per_blk = nq / FINB;               // 1024 queries
    const int qbase   = rank * per_blk;
    const float4* dm4 = (const float4*)g_dmin;   // 4 float4 per query

    float acc = 0.0f;
    #pragma unroll 2
    for (int i = tid; i < per_blk; i += THREADS) {
        const size_t base = (size_t)(qbase + i) * 4;
        const float4 d0 = dm4[base + 0];
        const float4 d1 = dm4[base + 1];
        const float4 d2 = dm4[base + 2];
        const float4 d3 = dm4[base + 3];
        const float m0 = fminf(fminf(d0.x, d0.y), fminf(d0.z, d0.w));
        const float m1 = fminf(fminf(d1.x, d1.y), fminf(d1.z, d1.w));
        const float m2 = fminf(fminf(d2.x, d2.y), fminf(d2.z, d2.w));
        const float m3 = fminf(fminf(d3.x, d3.y), fminf(d3.z, d3.w));
        const float dmn = fminf(fminf(m0, m1), fminf(m2, m3));
        const float sv = alpha * __powf(dmn, beta) + delta;
        acc += -sv * __expf(-sv);
    }

    #pragma unroll
    for (int o = 16; o > 0; o >>= 1)
        acc += __shfl_down_sync(0xffffffffu, acc, o);
    if ((tid & 31) == 0) red[tid >> 5] = acc;
    __syncthreads();

    if (tid == 0) {
        float v = 0.0f;
        #pragma unroll
        for (int w = 0; w < THREADS / 32; w++) v += red[w];
        g_fpart[rank] = v;
        __threadfence();
        const unsigned int t2 = atomicAdd(&g_ticket2, 1u);
        if (t2 == FINB - 1) {
            float total = 0.0f;
            #pragma unroll
            for (int r = 0; r < FINB; r++)
                total += *((volatile float*)&g_fpart[r]);
            out[0] = total * scale;
            g_work    = 0;       // self-clean for graph replay
            g_ticket1 = 0;
            g_ticket2 = 0;
        }
    }
}

extern "C" void kernel_launch(void* const* d_in, const int* in_sizes, int n_in,
                              void* d_out, int out_size)
{
    const float* a1    = (const float*)d_in[0];
    const float* a2    = (const float*)d_in[1];
    const float* alpha = (const float*)d_in[2];
    const float* beta  = (const float*)d_in[3];
    float* out = (float*)d_out;

    const int B  = in_sizes[0] / (NPTS * DIMS);
    const int nq = 2 * B * NPTS;
    const int nitems = 2 * B * 8 * SPLITS;       // 1024 at B=4
    const float scale = 50.0f / (float)B;

    gps_kernel<<<GRID, THREADS>>>(a1, a2, alpha, beta, out, nq, nitems, scale);
}